// round 15
// baseline (speedup 1.0000x reference)
#include <cuda_runtime.h>

#define KTAGS 48
#define PF 8
#define L2E 1.4426950408889634f
#define LN2 0.6931471805599453f

#define MAXB 4096
__device__ float g_wf[MAXB * KTAGS];
__device__ float g_wb[MAXB * KTAGS];
__device__ float g_c2f[MAXB];
__device__ float g_c2b[MAXB];
__device__ float g_path[MAXB];
__device__ float g_partial[64];
__device__ int   g_perm[MAXB];
__device__ unsigned g_done = 0;

__device__ __forceinline__ unsigned long long pk2(float lo, float hi) {
    unsigned long long r;
    asm("mov.b64 %0,{%1,%2};" : "=l"(r) : "f"(lo), "f"(hi));
    return r;
}
__device__ __forceinline__ void unpk2(unsigned long long v, float& a, float& b) {
    asm("mov.b64 {%0,%1},%2;" : "=f"(a), "=f"(b) : "l"(v));
}
__device__ __forceinline__ unsigned long long ffma2(unsigned long long a, unsigned long long b,
                                                    unsigned long long c) {
    unsigned long long d;
    asm("fma.rn.f32x2 %0,%1,%2,%3;" : "=l"(d) : "l"(a), "l"(b), "l"(c));
    return d;
}
__device__ __forceinline__ unsigned long long fadd2(unsigned long long a, unsigned long long b) {
    unsigned long long d;
    asm("add.rn.f32x2 %0,%1,%2;" : "=l"(d) : "l"(a), "l"(b));
    return d;
}
__device__ __forceinline__ float ex2f(float x) {
    float r; asm("ex2.approx.f32 %0,%1;" : "=f"(r) : "f"(x)); return r;
}
__device__ __forceinline__ float lg2f(float x) {
    float r; asm("lg2.approx.f32 %0,%1;" : "=f"(r) : "f"(x)); return r;
}
__device__ __forceinline__ float rcpf(float x) {
    float r; asm("rcp.approx.f32 %0,%1;" : "=f"(r) : "f"(x)); return r;
}

// Lane j: full dot for row j (EA, 24 ffma2) + HALF dot for row 32+(j>>1)
// (EC, 12 ffma2; element range picked by lane parity via the vc address),
// combined across the lane pair with one shfl_xor. 36 ffma2 total.
__device__ __forceinline__ void matvec48b(const unsigned long long* EA,
                                          const unsigned long long* EC,
                                          const float* svp, int coff,
                                          float& outA, float& outC) {
    const ulonglong2* vv = (const ulonglong2*)svp;
    const ulonglong2* vc = (const ulonglong2*)(svp + coff);
    unsigned long long z = pk2(0.0f, 0.0f);
    unsigned long long a0 = z, a1 = z, a2 = z, a3 = z, c0 = z, c1 = z;
#pragma unroll
    for (int q = 0; q < 6; q++) {
        ulonglong2 xe = vv[q];
        ulonglong2 xo = vv[q + 6];
        ulonglong2 xc = vc[q];
        a0 = ffma2(EA[2 * q],      xe.x, a0);
        a1 = ffma2(EA[2 * q + 1],  xe.y, a1);
        a2 = ffma2(EA[2 * q + 12], xo.x, a2);
        a3 = ffma2(EA[2 * q + 13], xo.y, a3);
        c0 = ffma2(EC[2 * q],      xc.x, c0);
        c1 = ffma2(EC[2 * q + 1],  xc.y, c1);
    }
    unsigned long long sA = fadd2(fadd2(a0, a1), fadd2(a2, a3));
    unsigned long long sC = fadd2(c0, c1);
    float lo, hi;
    unpk2(sA, lo, hi); outA = lo + hi;
    unpk2(sC, lo, hi);
    float pc = lo + hi;
    pc += __shfl_xor_sync(0xffffffffu, pc, 1);
    outC = pc;
}

// Parallel rank: rank b = #{k: L_k>L_b || (== && k<b)}. g_perm[rank]=b.
__global__ void crf_rank(const int* __restrict__ lengths, int B, int T) {
    __shared__ int sl[1024];
    for (int k = threadIdx.x; k < B; k += blockDim.x) {
        int L = lengths[k];
        sl[k] = L < 1 ? 1 : (L > T ? T : L);
    }
    __syncthreads();
    const int lane = threadIdx.x & 31;
    const int nw = (gridDim.x * blockDim.x) >> 5;
    for (int b = (blockIdx.x * blockDim.x + threadIdx.x) >> 5; b < B; b += nw) {
        int Lb = sl[b];
        int cnt = 0;
        for (int k = lane; k < B; k += 32) {
            int Lk = sl[k];
            cnt += (Lk > Lb) || (Lk == Lb && k < b);
        }
#pragma unroll
        for (int s = 16; s > 0; s >>= 1) cnt += __shfl_xor_sync(0xffffffffu, cnt, s);
        if (lane == 0) g_perm[cnt] = b;
    }
}

// Makespan-balanced bidirectional CRF: CTA i runs forward alpha 0..m of batch
// perm[i], then backward beta L-1..m of batch perm[B-1-i]; L_i + L_{B-1-i} ~
// const after ranking, so all CTAs do ~T/2 serial steps at 512 CTAs.
__global__ void __launch_bounds__(32) crf_bidir(
    const float* __restrict__ emis,   // [B, T, K]
    const int* __restrict__ lengths,  // [B]
    const int* __restrict__ tags,     // [B, T]
    const float* __restrict__ prior,  // [K]
    const float* __restrict__ trans,  // [K, K]
    const float* __restrict__ ftrans, // [K]
    int B, int T)
{
    __shared__ __align__(16) float sv[2][KTAGS];

    const int j = threadIdx.x;
    const int rA = j;
    const int rC = 32 + (j >> 1);
    const bool even = (j & 1) == 0;
    const int cbase = (j & 1) ? 24 : 0;   // element range of the half-row

    // ================= phase 1: forward =================
    {
        const int b = g_perm[blockIdx.x];
        int L = lengths[b];
        if (L < 1) L = 1;
        if (L > T) L = T;
        const int m = L >> 1;
        const float* eb = emis + (size_t)b * T * KTAGS;

        unsigned long long EA[24], EC[12];
        {
            const float4* trA = (const float4*)(trans + rA * KTAGS);
#pragma unroll
            for (int q = 0; q < 12; q++) {
                float4 va = trA[q];
                EA[2 * q]     = pk2(ex2f(va.x * L2E), ex2f(va.y * L2E));
                EA[2 * q + 1] = pk2(ex2f(va.z * L2E), ex2f(va.w * L2E));
            }
            const float* trC = trans + rC * KTAGS + cbase;
#pragma unroll
            for (int q = 0; q < 12; q++)
                EC[q] = pk2(ex2f(trC[2 * q] * L2E), ex2f(trC[2 * q + 1] * L2E));
        }

        float aA = eb[rA] + prior[rA];
        float aC = eb[rC] + prior[rC];
        float m0 = __shfl_sync(0xffffffffu, aA, 0);
        float C2 = m0 * L2E;
        float wA = ex2f((aA - m0) * L2E);
        float wC = ex2f((aC - m0) * L2E);
        sv[0][rA] = wA;
        if (even) sv[0][rC] = wC;
        __syncwarp();
        int p = 0;

        const int Lf = m + 1;   // consume t = 1..m
        float rawA[PF], rawC[PF];
#pragma unroll
        for (int d = 0; d < PF; d++) {
            int t = 1 + d;
            rawA[d] = (t < Lf) ? eb[(size_t)t * KTAGS + rA] : 0.0f;
            rawC[d] = (t < Lf) ? eb[(size_t)t * KTAGS + rC] : 0.0f;
        }

        int t0 = 1;
        // phase 1a: branch-free full blocks
        {
            const float* bA = eb + (size_t)(1 + PF) * KTAGS + rA;
            const float* bC = eb + (size_t)(1 + PF) * KTAGS + rC;
            for (; t0 + 2 * PF <= Lf; t0 += PF) {
#pragma unroll
                for (int d = 0; d < PF; d++) {
                    float eetA = ex2f(rawA[d] * L2E);
                    float eetC = ex2f(rawC[d] * L2E);
                    rawA[d] = bA[d * KTAGS];
                    rawC[d] = bC[d * KTAGS];

                    float gA = eetA, gC = eetC;
                    if ((d & 3) == 0) {
                        float r = __shfl_sync(0xffffffffu, wA, 0);
                        float rr = rcpf(r);
                        C2 += lg2f(r);
                        gA = eetA * rr;
                        gC = eetC * rr;
                    }

                    float uA, uC;
                    matvec48b(EA, EC, sv[p], cbase, uA, uC);
                    wA = uA * gA;
                    wC = uC * gC;

                    const int q2 = p ^ 1;
                    sv[q2][rA] = wA;
                    if (even) sv[q2][rC] = wC;
                    __syncwarp();
                    p = q2;
                }
                bA += PF * KTAGS;
                bC += PF * KTAGS;
            }
        }
        // phase 1b: predicated tail
        for (; t0 < Lf; t0 += PF) {
#pragma unroll
            for (int d = 0; d < PF; d++) {
                const int t = t0 + d;
                if (t >= Lf) break;

                float eetA = ex2f(rawA[d] * L2E);
                float eetC = ex2f(rawC[d] * L2E);
                {
                    int tn = t + PF;
                    rawA[d] = (tn < Lf) ? eb[(size_t)tn * KTAGS + rA] : 0.0f;
                    rawC[d] = (tn < Lf) ? eb[(size_t)tn * KTAGS + rC] : 0.0f;
                }

                float gA = eetA, gC = eetC;
                if ((d & 3) == 0) {
                    float r = __shfl_sync(0xffffffffu, wA, 0);
                    float rr = rcpf(r);
                    C2 += lg2f(r);
                    gA = eetA * rr;
                    gC = eetC * rr;
                }

                float uA, uC;
                matvec48b(EA, EC, sv[p], cbase, uA, uC);
                wA = uA * gA;
                wC = uC * gC;

                const int q2 = p ^ 1;
                sv[q2][rA] = wA;
                if (even) sv[q2][rC] = wC;
                __syncwarp();
                p = q2;
            }
        }

        g_wf[b * KTAGS + rA] = wA;
        if (even) g_wf[b * KTAGS + rC] = wC;
        if (j == 0) g_c2f[b] = C2;

        // path score over full L
        const int* tb = tags + (size_t)b * T;
        float acc = 0.0f;
        for (int t = j; t < L; t += 32) {
            int tg = min(max(tb[t], 0), KTAGS - 1);
            float tr = (t == 0) ? prior[tg]
                                : trans[tg * KTAGS + min(max(tb[t - 1], 0), KTAGS - 1)];
            acc += eb[(size_t)t * KTAGS + tg] + tr;
        }
#pragma unroll
        for (int s = 16; s > 0; s >>= 1)
            acc += __shfl_xor_sync(0xffffffffu, acc, s);
        if (j == 0)
            g_path[b] = acc + ftrans[min(max(tb[L - 1], 0), KTAGS - 1)];
    }

    // ================= phase 2: backward =================
    {
        const int b = g_perm[B - 1 - blockIdx.x];
        int L = lengths[b];
        if (L < 1) L = 1;
        if (L > T) L = T;
        const int m = L >> 1;
        const float* eb = emis + (size_t)b * T * KTAGS;

        unsigned long long EA[24], EC[12];
#pragma unroll
        for (int q = 0; q < 24; q++) {
            int j0 = 2 * q, j1 = 2 * q + 1;
            EA[q] = pk2(ex2f(trans[j0 * KTAGS + rA] * L2E),
                        ex2f(trans[j1 * KTAGS + rA] * L2E));
        }
#pragma unroll
        for (int q = 0; q < 12; q++) {
            int j0 = cbase + 2 * q, j1 = cbase + 2 * q + 1;
            EC[q] = pk2(ex2f(trans[j0 * KTAGS + rC] * L2E),
                        ex2f(trans[j1 * KTAGS + rC] * L2E));
        }

        float C2 = 0.0f;
        float vbA, vbC;

        if (m == L - 1) {
            vbA = ex2f(ftrans[rA] * L2E);
            vbC = ex2f(ftrans[rC] * L2E);
        } else {
            float zA = ex2f((ftrans[rA] + eb[(size_t)(L - 1) * KTAGS + rA]) * L2E);
            float zC = ex2f((ftrans[rC] + eb[(size_t)(L - 1) * KTAGS + rC]) * L2E);
            int p = 0;

            const int nsteps = L - 1 - m;
            const int nfull = nsteps - 1;

            float rawA[PF], rawC[PF];
#pragma unroll
            for (int d = 0; d < PF; d++) {
                int t = L - 2 - d;
                rawA[d] = (d < nfull) ? eb[(size_t)t * KTAGS + rA] : 0.0f;
                rawC[d] = (d < nfull) ? eb[(size_t)t * KTAGS + rC] : 0.0f;
            }

            int s0 = 0;
            // phase 2a: branch-free full blocks
            if (2 * PF <= nfull) {
                const float* bA = eb + (size_t)(L - 2 - PF) * KTAGS + rA;
                const float* bC = eb + (size_t)(L - 2 - PF) * KTAGS + rC;
                for (; s0 + 2 * PF <= nfull; s0 += PF) {
#pragma unroll
                    for (int d = 0; d < PF; d++) {
                        float eetA = ex2f(rawA[d] * L2E);
                        float eetC = ex2f(rawC[d] * L2E);
                        rawA[d] = *(bA - d * KTAGS);
                        rawC[d] = *(bC - d * KTAGS);

                        float gA = eetA, gC = eetC;
                        if ((d & 3) == 0) {
                            float r = __shfl_sync(0xffffffffu, zA, 0);
                            float rr = rcpf(r);
                            C2 += lg2f(r);
                            gA = eetA * rr;
                            gC = eetC * rr;
                        }

                        const int pn = p ^ 1;
                        sv[pn][rA] = zA * gA;
                        if (even) sv[pn][rC] = zC * gC;
                        __syncwarp();
                        float uA, uC;
                        matvec48b(EA, EC, sv[pn], cbase, uA, uC);
                        zA = uA;
                        zC = uC;
                        p = pn;
                    }
                    bA -= PF * KTAGS;
                    bC -= PF * KTAGS;
                }
            }
            // phase 2b: predicated tail
            for (; s0 < nfull; s0 += PF) {
#pragma unroll
                for (int d = 0; d < PF; d++) {
                    const int s = s0 + d;
                    if (s >= nfull) break;
                    const int t = L - 2 - s;

                    float eetA = ex2f(rawA[d] * L2E);
                    float eetC = ex2f(rawC[d] * L2E);
                    {
                        int sn = s + PF;
                        int tn = t - PF;
                        rawA[d] = (sn < nfull) ? eb[(size_t)tn * KTAGS + rA] : 0.0f;
                        rawC[d] = (sn < nfull) ? eb[(size_t)tn * KTAGS + rC] : 0.0f;
                    }

                    float gA = eetA, gC = eetC;
                    if ((d & 3) == 0) {
                        float r = __shfl_sync(0xffffffffu, zA, 0);
                        float rr = rcpf(r);
                        C2 += lg2f(r);
                        gA = eetA * rr;
                        gC = eetC * rr;
                    }

                    const int pn = p ^ 1;
                    sv[pn][rA] = zA * gA;
                    if (even) sv[pn][rC] = zC * gC;
                    __syncwarp();
                    float uA, uC;
                    matvec48b(EA, EC, sv[pn], cbase, uA, uC);
                    zA = uA;
                    zC = uC;
                    p = pn;
                }
            }
            // final step (t = m): matvec only
            const int pn = p ^ 1;
            sv[pn][rA] = zA;
            if (even) sv[pn][rC] = zC;
            __syncwarp();
            matvec48b(EA, EC, sv[pn], cbase, vbA, vbC);
        }

        g_wb[b * KTAGS + rA] = vbA;
        if (even) g_wb[b * KTAGS + rC] = vbC;
        if (j == 0) g_c2b[b] = C2;
    }
}

// Fused combine + final mean (last-block pattern; counter self-resets so the
// kernel is deterministic across graph replays).
__global__ void crf_combine(float* __restrict__ out, int B) {
    __shared__ float sh[8];
    __shared__ int lastFlag;
    const int tid = threadIdx.x;
    const int wid = tid >> 5, j = tid & 31;
    const int gw = blockIdx.x * 8 + wid;
    float v = 0.0f;
    for (int b = gw; b < B; b += 256) {
        float d = g_wf[b * KTAGS + j] * g_wb[b * KTAGS + j];
        if (j < 16) d += g_wf[b * KTAGS + 32 + j] * g_wb[b * KTAGS + 32 + j];
#pragma unroll
        for (int s = 16; s > 0; s >>= 1) d += __shfl_xor_sync(0xffffffffu, d, s);
        if (j == 0)
            v += (lg2f(d) + g_c2f[b] + g_c2b[b]) * LN2 - g_path[b];
    }
    if (j == 0) sh[wid] = v;
    __syncthreads();
    if (tid == 0) {
        float s = 0.0f;
#pragma unroll
        for (int k = 0; k < 8; k++) s += sh[k];
        g_partial[blockIdx.x] = s;
        __threadfence();
        unsigned prev = atomicAdd(&g_done, 1u);
        lastFlag = (prev == 31u);
    }
    __syncthreads();
    if (lastFlag && tid < 32) {
        __threadfence();
        float v2 = g_partial[tid];
#pragma unroll
        for (int s = 16; s > 0; s >>= 1) v2 += __shfl_xor_sync(0xffffffffu, v2, s);
        if (tid == 0) {
            out[0] = v2 / (float)B;
            g_done = 0;   // reset for next graph replay
        }
    }
}

extern "C" void kernel_launch(void* const* d_in, const int* in_sizes, int n_in,
                              void* d_out, int out_size) {
    const float* emis    = (const float*)d_in[0];
    const int*   lengths = (const int*)d_in[1];
    const int*   tags    = (const int*)d_in[2];
    const float* prior   = (const float*)d_in[3];
    const float* trans   = (const float*)d_in[4];
    const float* ftrans  = (const float*)d_in[5];

    const int B = in_sizes[1];              // lengths count
    const int T = in_sizes[2] / B;          // tags = [B, T]

    crf_rank<<<16, 256>>>(lengths, B, T);
    crf_bidir<<<B, 32>>>(emis, lengths, tags, prior, trans, ftrans, B, T);
    crf_combine<<<32, 256>>>((float*)d_out, B);
}